// round 12
// baseline (speedup 1.0000x reference)
#include <cuda_runtime.h>
#include <cstdint>

// ---------------------------------------------------------------------------
// Skeletonize — bit-packed (u32 words) thinning, full-occupancy passes.
//   padded grid: (2,162,162,162); packed along z: 6 x u32 per (b,X,Y) row
//   RNG: JAX threefry_partitionable: counter (0, flat_index), bits = o0 ^ o1
// ---------------------------------------------------------------------------

#define NPAD 162
#define ROWS_PER_BATCH (162*162)        // 26244
#define NROWS (2*ROWS_PER_BATCH)        // 52488
#define WPRW 6                          // u32 words per row (192 bits, 162 used)
#define HALF 4251528u                   // 162^3

typedef unsigned int u32;

__device__ u32 g_img[NROWS*WPRW];
__device__ u32 g_end[NROWS*WPRW];

__device__ __forceinline__ u32 rotl32(u32 x, int r){ return (x<<r)|(x>>(32-r)); }

// JAX threefry2x32, key (0,42), partitionable combine
__device__ __forceinline__ u32 threefry_xor(u32 x0, u32 x1){
  const u32 ks1 = 42u;
  const u32 ks2 = 0x1BD11BDAu ^ 42u;
  x0 += 0u; x1 += ks1;
#define TF_RND(r) { x0 += x1; x1 = rotl32(x1, (r)); x1 ^= x0; }
  TF_RND(13) TF_RND(15) TF_RND(26) TF_RND(6)
  x0 += ks1; x1 += ks2 + 1u;
  TF_RND(17) TF_RND(29) TF_RND(16) TF_RND(24)
  x0 += ks2; x1 += 2u;
  TF_RND(13) TF_RND(15) TF_RND(26) TF_RND(6)
  x0 += 0u;  x1 += ks1 + 3u;
  TF_RND(17) TF_RND(29) TF_RND(16) TF_RND(24)
  x0 += ks1; x1 += ks2 + 4u;
  TF_RND(13) TF_RND(15) TF_RND(26) TF_RND(6)
  x0 += ks2; x1 += 5u;
#undef TF_RND
  return x0 ^ x1;
}

__device__ __forceinline__ int hard_bit(u32 bits, float img){
  float f = __fadd_rn(__uint_as_float((bits >> 9) | 0x3f800000u), -1.0f);
  float u = __fadd_rn(__fmul_rn(f, 1.0f), 1e-8f);
  u = fmaxf(1e-8f, u);
  float noise = __fadd_rn(logf(u), -log1pf(-u));
  float alpha = __fdiv_rn(__fadd_rn(img, 1e-8f),
                          __fadd_rn(__fadd_rn(1.0f, -img), 1e-8f));
  float zv = __fadd_rn(logf(alpha), __fmul_rn(noise, 0.33f));
  return zv > 0.0f;
}

__global__ void k_binarize(const float* __restrict__ in){
  int gt = blockIdx.x*blockDim.x + threadIdx.x;
  int W = gt >> 5;
  int lane = gt & 31;
  if (W >= ROWS_PER_BATCH*6) return;
  int r0 = W / 6, k = W % 6;
  int X = r0 / NPAD, Y = r0 % NPAD;
  int z = k*32 + lane;
  bool valid = (z < NPAD);
  u32 i = (u32)r0 * (u32)NPAD + (u32)(valid ? z : 0);
  u32 b0bits = threefry_xor(0u, i);
  u32 b1bits = threefry_xor(0u, i + HALF);
  bool interior = valid && X>=1 && X<=160 && Y>=1 && Y<=160 && z>=1 && z<=160;
  float v0 = 0.f, v1 = 0.f;
  if (interior){
    int ui = ((X-1)*160 + (Y-1))*160 + (z-1);
    v0 = in[ui];
    v1 = in[ui + 160*160*160];
  }
  int h0 = hard_bit(b0bits, v0);
  int h1 = hard_bit(b1bits, v1);
  u32 m0 = __ballot_sync(0xFFFFFFFFu, valid && h0);
  u32 m1 = __ballot_sync(0xFFFFFFFFu, valid && h1);
  if (lane == 0){
    g_img[(size_t)r0*WPRW + k] = m0;
    g_img[(size_t)(ROWS_PER_BATCH + r0)*WPRW + k] = m1;
  }
}

#define SAT(one, ge, x) { u32 _x=(x); (ge) |= (one) & _x; (one) |= _x; }

__global__ void __launch_bounds__(256) k_endpoint(){
  int t = blockIdx.x*blockDim.x + threadIdx.x;
  if (t >= NROWS*WPRW) return;
  int w = t % WPRW; int r = t / WPRW;
  int Y = r % NPAD; int rX = r / NPAD; int X = rX % NPAD; int b = rX / NPAD;
  u32 one=0, ge=0;
  #pragma unroll
  for (int i=0;i<3;i++){
    #pragma unroll
    for (int j=0;j<3;j++){
      int XX = X + i - 1, YY = Y + j - 1;
      bool ok = (XX>=0 && XX<NPAD && YY>=0 && YY<NPAD);
      const u32* row = g_img + (size_t)((b*NPAD + XX)*NPAD + YY)*WPRW;
      u32 wm = (ok && w>0)      ? row[w-1] : 0u;
      u32 wc =  ok              ? row[w]   : 0u;
      u32 wp = (ok && w<WPRW-1) ? row[w+1] : 0u;
      u32 M = (wc<<1) | (wm>>31);
      u32 P = (wc>>1) | (wp<<31);
      SAT(one, ge, M);
      if (!(i==1 && j==1)) SAT(one, ge, wc);
      SAT(one, ge, P);
    }
  }
  g_end[t] = ~ge;            // bit=1 <=> n26 <= 1
}

__global__ void __launch_bounds__(128) k_simple(int xo, int yo, int zo){
  int t = blockIdx.x*blockDim.x + threadIdx.x;
  if (t >= 2*81*81*WPRW) return;
  int w = t % WPRW; int q = t / WPRW;
  int Yi = q % 81; q /= 81;
  int Xi = q % 81; int b = q / 81;
  int X = xo + 2*Xi, Y = yo + 2*Yi;

  u32 A[3][3][3];
  #pragma unroll
  for (int i=0;i<3;i++){
    #pragma unroll
    for (int j=0;j<3;j++){
      int XX = X + i - 1, YY = Y + j - 1;
      bool ok = (XX>=0 && XX<NPAD && YY>=0 && YY<NPAD);
      const u32* row = g_img + (size_t)((b*NPAD + XX)*NPAD + YY)*WPRW;
      u32 wm = (ok && w>0)      ? row[w-1] : 0u;
      u32 wc =  ok              ? row[w]   : 0u;
      u32 wp = (ok && w<WPRW-1) ? row[w+1] : 0u;
      A[i][j][0] = (wc<<1) | (wm>>31);
      A[i][j][1] = wc;
      A[i][j][2] = (wc>>1) | (wp<<31);
    }
  }

  u32 one18=0, ge18=0;
  #pragma unroll
  for (int i=0;i<3;i++){
    #pragma unroll
    for (int j=0;j<3;j++){
      #pragma unroll
      for (int k=0;k<3;k++){
        int c = (i==1?0:1)+(j==1?0:1)+(k==1?0:1);
        if (c==1 || c==2) SAT(one18, ge18, A[i][j][k]);
      }
    }
  }
  u32 one26=one18, ge26=ge18;
  #pragma unroll
  for (int i=0;i<3;i+=2){
    #pragma unroll
    for (int j=0;j<3;j+=2){
      #pragma unroll
      for (int k=0;k<3;k+=2) SAT(one26, ge26, A[i][j][k]);
    }
  }
  u32 one6=0, ge6=0;
  SAT(one6, ge6, ~A[0][1][1]); SAT(one6, ge6, ~A[2][1][1]);
  SAT(one6, ge6, ~A[1][0][1]); SAT(one6, ge6, ~A[1][2][1]);
  SAT(one6, ge6, ~A[1][1][0]); SAT(one6, ge6, ~A[1][1][2]);

  u32 anyB = 0;
  #pragma unroll
  for (int i=0;i<3;i+=2){
    #pragma unroll
    for (int j=0;j<3;j+=2){
      #pragma unroll
      for (int k=0;k<3;k+=2){
        u32 others = A[i][1][1] | A[1][j][1] | A[1][1][k]
                   | A[i][j][1] | A[i][1][k] | A[1][j][k];
        anyB |= A[i][j][k] & ~others;
      }
    }
  }
  u32 anyA = 0;
  #pragma unroll
  for (int s=0;s<3;s+=2){
    anyA |= ~A[s][1][1] & A[s][0][1] & A[s][2][1] & A[s][1][0] & A[s][1][2];
    anyA |= ~A[1][s][1] & A[0][s][1] & A[2][s][1] & A[1][s][0] & A[1][s][2];
    anyA |= ~A[1][1][s] & A[0][1][s] & A[2][1][s] & A[1][0][s] & A[1][2][s];
  }

  u32 notB = ~anyB;
  u32 simple = (one6 & ~ge6)
             | (one26 & ~ge26)
             | (one18 & ~ge18 & notB)
             | (ge6 & ~anyA & notB);
  u32 zmask = (zo==0) ? 0x55555555u : 0xAAAAAAAAu;   // word base 32w is even
  size_t idx = (size_t)((b*NPAD + X)*NPAD + Y)*WPRW + w;
  u32 del = simple & ~g_end[idx] & zmask;
  if (del) g_img[idx] &= ~del;
}

__global__ void k_unpack(float* __restrict__ out){
  int t = blockIdx.x*blockDim.x + threadIdx.x;
  if (t >= 2*160*160*160) return;
  int z = t % 160; int q = t/160;
  int y = q % 160; q /= 160;
  int x = q % 160; int b = q / 160;
  int zz = z + 1;
  size_t row = (size_t)((b*NPAD + (x+1))*NPAD + (y+1));
  u32 wv = g_img[row*WPRW + (zz>>5)];
  out[t] = (float)((wv >> (zz & 31)) & 1u);
}

extern "C" void kernel_launch(void* const* d_in, const int* in_sizes, int n_in,
                              void* d_out, int out_size){
  const float* in = (const float*)d_in[0];
  float* out = (float*)d_out;
  (void)in_sizes; (void)n_in; (void)out_size;

  k_binarize<<<19683, 256>>>(in);

  static const int OFF[8][3] = {{0,0,0},{1,0,0},{0,1,0},{1,1,0},
                                {0,0,1},{1,0,1},{0,1,1},{1,1,1}};
  const int nword = NROWS*WPRW;             // 314928
  const int nsub  = 2*81*81*WPRW;           // 78732
  for (int it = 0; it < 5; ++it){
    k_endpoint<<<(nword+255)/256, 256>>>();
    for (int o = 0; o < 8; ++o)
      k_simple<<<(nsub+127)/128, 128>>>(OFF[o][0], OFF[o][1], OFF[o][2]);
  }

  k_unpack<<<(2*160*160*160 + 255)/256, 256>>>(out);
}

// round 14
// speedup vs baseline: 1.3651x; 1.3651x over previous
#include <cuda_runtime.h>
#include <cstdint>

// ---------------------------------------------------------------------------
// Skeletonize — bit-packed u64, PLANAR (SoA) layout, Y-fastest threads.
//   g_img[w][b][X][Y]: plane per z-word (w=0..2), Y contiguous.
//   RNG: JAX threefry_partitionable: counter (0, flat_index), bits = o0 ^ o1
// ---------------------------------------------------------------------------

#define NPAD 162
#define ROWS_PER_BATCH (162*162)        // 26244
#define NROWS (2*ROWS_PER_BATCH)        // 52488
#define WPR 3
#define HALF 4251528u                   // 162^3

typedef unsigned long long u64;
typedef unsigned int u32;

__device__ u64 g_img[WPR*NROWS];        // plane-major
__device__ u64 g_end[WPR*NROWS];

#define IMGIDX(w,b,X,Y) ((size_t)(w)*NROWS + (size_t)((b)*NPAD + (X))*NPAD + (Y))

__device__ __forceinline__ u32 rotl32(u32 x, int r){ return (x<<r)|(x>>(32-r)); }

// JAX threefry2x32, key (0,42), partitionable combine
__device__ __forceinline__ u32 threefry_xor(u32 x0, u32 x1){
  const u32 ks1 = 42u;
  const u32 ks2 = 0x1BD11BDAu ^ 42u;
  x0 += 0u; x1 += ks1;
#define TF_RND(r) { x0 += x1; x1 = rotl32(x1, (r)); x1 ^= x0; }
  TF_RND(13) TF_RND(15) TF_RND(26) TF_RND(6)
  x0 += ks1; x1 += ks2 + 1u;
  TF_RND(17) TF_RND(29) TF_RND(16) TF_RND(24)
  x0 += ks2; x1 += 2u;
  TF_RND(13) TF_RND(15) TF_RND(26) TF_RND(6)
  x0 += 0u;  x1 += ks1 + 3u;
  TF_RND(17) TF_RND(29) TF_RND(16) TF_RND(24)
  x0 += ks1; x1 += ks2 + 4u;
  TF_RND(13) TF_RND(15) TF_RND(26) TF_RND(6)
  x0 += ks2; x1 += 5u;
#undef TF_RND
  return x0 ^ x1;
}

__device__ __forceinline__ int hard_bit(u32 bits, float img){
  float f = __fadd_rn(__uint_as_float((bits >> 9) | 0x3f800000u), -1.0f);
  float u = __fadd_rn(__fmul_rn(f, 1.0f), 1e-8f);
  u = fmaxf(1e-8f, u);
  float noise = __fadd_rn(logf(u), -log1pf(-u));
  float alpha = __fdiv_rn(__fadd_rn(img, 1e-8f),
                          __fadd_rn(__fadd_rn(1.0f, -img), 1e-8f));
  float zv = __fadd_rn(logf(alpha), __fmul_rn(noise, 0.33f));
  return zv > 0.0f;
}

__global__ void k_binarize(const float* __restrict__ in){
  int gt = blockIdx.x*blockDim.x + threadIdx.x;
  int W = gt >> 5;
  int lane = gt & 31;
  if (W >= ROWS_PER_BATCH*6) return;
  int r0 = W / 6, k = W % 6;
  int X = r0 / NPAD, Y = r0 % NPAD;
  int z = k*32 + lane;
  bool valid = (z < NPAD);
  u32 i = (u32)r0 * (u32)NPAD + (u32)(valid ? z : 0);
  u32 b0bits = threefry_xor(0u, i);
  u32 b1bits = threefry_xor(0u, i + HALF);
  bool interior = valid && X>=1 && X<=160 && Y>=1 && Y<=160 && z>=1 && z<=160;
  float v0 = 0.f, v1 = 0.f;
  if (interior){
    int ui = ((X-1)*160 + (Y-1))*160 + (z-1);
    v0 = in[ui];
    v1 = in[ui + 160*160*160];
  }
  int h0 = hard_bit(b0bits, v0);
  int h1 = hard_bit(b1bits, v1);
  u32 m0 = __ballot_sync(0xFFFFFFFFu, valid && h0);
  u32 m1 = __ballot_sync(0xFFFFFFFFu, valid && h1);
  if (lane == 0){
    int w = k >> 1, half = k & 1;
    u32* p = (u32*)g_img;
    p[(((size_t)w*NROWS) + r0)*2 + half] = m0;                       // batch 0
    p[(((size_t)w*NROWS) + ROWS_PER_BATCH + r0)*2 + half] = m1;      // batch 1
  }
}

#define SAT(one, ge, x) { u64 _x=(x); (ge) |= (one) & _x; (one) |= _x; }

// thread t: Y fastest, then X, then b, then w  (warp lanes contiguous in Y)
__global__ void __launch_bounds__(256) k_endpoint(){
  int t = blockIdx.x*blockDim.x + threadIdx.x;
  if (t >= WPR*NROWS) return;
  int Y = t % NPAD; int s = t / NPAD;
  int X = s % NPAD; s /= NPAD;
  int b = s % 2;   int w = s / 2;
  u64 one=0, ge=0;
  #pragma unroll
  for (int i=0;i<3;i++){
    #pragma unroll
    for (int j=0;j<3;j++){
      int XX = X + i - 1, YY = Y + j - 1;
      bool ok = (XX>=0 && XX<NPAD && YY>=0 && YY<NPAD);
      u64 wm = (ok && w>0)     ? g_img[IMGIDX(w-1,b,XX,YY)] : 0ull;
      u64 wc =  ok             ? g_img[IMGIDX(w  ,b,XX,YY)] : 0ull;
      u64 wp = (ok && w<WPR-1) ? g_img[IMGIDX(w+1,b,XX,YY)] : 0ull;
      u64 M = (wc<<1) | (wm>>63);
      u64 P = (wc>>1) | (wp<<63);
      SAT(one, ge, M);
      if (!(i==1 && j==1)) SAT(one, ge, wc);
      SAT(one, ge, P);
    }
  }
  g_end[IMGIDX(w,b,X,Y)] = ~ge;          // bit=1 <=> n26 <= 1
}

// thread t: Yi fastest, then Xi, then b, then w
__global__ void __launch_bounds__(256) k_simple(int xo, int yo, int zo){
  int t = blockIdx.x*blockDim.x + threadIdx.x;
  if (t >= WPR*2*81*81) return;
  int Yi = t % 81; int s = t / 81;
  int Xi = s % 81; s /= 81;
  int b = s % 2;  int w = s / 2;
  int X = xo + 2*Xi, Y = yo + 2*Yi;

  u64 A[3][3][3];
  #pragma unroll
  for (int i=0;i<3;i++){
    #pragma unroll
    for (int j=0;j<3;j++){
      int XX = X + i - 1, YY = Y + j - 1;
      bool ok = (XX>=0 && XX<NPAD && YY>=0 && YY<NPAD);
      u64 wm = (ok && w>0)     ? g_img[IMGIDX(w-1,b,XX,YY)] : 0ull;
      u64 wc =  ok             ? g_img[IMGIDX(w  ,b,XX,YY)] : 0ull;
      u64 wp = (ok && w<WPR-1) ? g_img[IMGIDX(w+1,b,XX,YY)] : 0ull;
      A[i][j][0] = (wc<<1) | (wm>>63);
      A[i][j][1] = wc;
      A[i][j][2] = (wc>>1) | (wp<<63);
    }
  }

  u64 one18=0, ge18=0;
  #pragma unroll
  for (int i=0;i<3;i++){
    #pragma unroll
    for (int j=0;j<3;j++){
      #pragma unroll
      for (int k=0;k<3;k++){
        int c = (i==1?0:1)+(j==1?0:1)+(k==1?0:1);
        if (c==1 || c==2) SAT(one18, ge18, A[i][j][k]);
      }
    }
  }
  u64 one26=one18, ge26=ge18;
  #pragma unroll
  for (int i=0;i<3;i+=2){
    #pragma unroll
    for (int j=0;j<3;j+=2){
      #pragma unroll
      for (int k=0;k<3;k+=2) SAT(one26, ge26, A[i][j][k]);
    }
  }
  u64 one6=0, ge6=0;
  SAT(one6, ge6, ~A[0][1][1]); SAT(one6, ge6, ~A[2][1][1]);
  SAT(one6, ge6, ~A[1][0][1]); SAT(one6, ge6, ~A[1][2][1]);
  SAT(one6, ge6, ~A[1][1][0]); SAT(one6, ge6, ~A[1][1][2]);

  u64 anyB = 0;
  #pragma unroll
  for (int i=0;i<3;i+=2){
    #pragma unroll
    for (int j=0;j<3;j+=2){
      #pragma unroll
      for (int k=0;k<3;k+=2){
        u64 others = A[i][1][1] | A[1][j][1] | A[1][1][k]
                   | A[i][j][1] | A[i][1][k] | A[1][j][k];
        anyB |= A[i][j][k] & ~others;
      }
    }
  }
  u64 anyA = 0;
  #pragma unroll
  for (int s2=0;s2<3;s2+=2){
    anyA |= ~A[s2][1][1] & A[s2][0][1] & A[s2][2][1] & A[s2][1][0] & A[s2][1][2];
    anyA |= ~A[1][s2][1] & A[0][s2][1] & A[2][s2][1] & A[1][s2][0] & A[1][s2][2];
    anyA |= ~A[1][1][s2] & A[0][1][s2] & A[2][1][s2] & A[1][0][s2] & A[1][2][s2];
  }

  u64 notB = ~anyB;
  u64 simple = (one6 & ~ge6)
             | (one26 & ~ge26)
             | (one18 & ~ge18 & notB)
             | (ge6 & ~anyA & notB);
  u64 zmask = (zo==0) ? 0x5555555555555555ull : 0xAAAAAAAAAAAAAAAAull;
  size_t idx = IMGIDX(w,b,X,Y);
  u64 del = simple & ~g_end[idx] & zmask;
  if (del) g_img[idx] &= ~del;
}

__global__ void k_unpack(float* __restrict__ out){
  int t = blockIdx.x*blockDim.x + threadIdx.x;
  if (t >= 2*160*160*160) return;
  int z = t % 160; int q = t/160;
  int y = q % 160; q /= 160;
  int x = q % 160; int b = q / 160;
  int zz = z + 1;
  u64 wv = g_img[IMGIDX(zz>>6, b, x+1, y+1)];
  out[t] = (float)((wv >> (zz & 63)) & 1ull);
}

extern "C" void kernel_launch(void* const* d_in, const int* in_sizes, int n_in,
                              void* d_out, int out_size){
  const float* in = (const float*)d_in[0];
  float* out = (float*)d_out;
  (void)in_sizes; (void)n_in; (void)out_size;

  k_binarize<<<19683, 256>>>(in);

  static const int OFF[8][3] = {{0,0,0},{1,0,0},{0,1,0},{1,1,0},
                                {0,0,1},{1,0,1},{0,1,1},{1,1,1}};
  const int nword = WPR*NROWS;              // 157464
  const int nsub  = WPR*2*81*81;            // 39366
  for (int it = 0; it < 5; ++it){
    k_endpoint<<<(nword+255)/256, 256>>>();
    for (int o = 0; o < 8; ++o)
      k_simple<<<(nsub+255)/256, 256>>>(OFF[o][0], OFF[o][1], OFF[o][2]);
  }

  k_unpack<<<(2*160*160*160 + 255)/256, 256>>>(out);
}